// round 11
// baseline (speedup 1.0000x reference)
#include <cuda_runtime.h>
#include <cuda_fp16.h>
#include <cstdint>

// out = softmax(normalize(Q)@normalize(K)^T) @ K,  N=65536, K=4096, D=128, fp32
// fp16 mma.sync dataflow (proven, rel_err 9.5e-5):
//   S  = Qn @ Kn^T  (non-trans ldsm4 on [key][d] tile)   [Qn prescaled by log2e]
//   O += (exp2(S)-1) @ V  (non-trans ldsm4 on V^T [d][key] tile)
//   out = (colsum(V) + O) / Z
// R10: register diet (JIT ldsm, 2 S-chains) + 2-stage pipeline =>
//      3 CTAs/SM (12 warps) to fix the latency-bound low-occupancy profile.

#define NQ 65536
#define NKEY 4096
#define DIM 128
#define BM 64
#define BK 64
#define NTILES (NKEY / BK)
#define NTHREADS 128
#define SROWK 272         // K tile row stride bytes (128 fp16 + 16B pad)
#define SROWV 144         // V^T tile row stride bytes (64 fp16 + 16B pad)

__device__ __align__(16) __half g_Qh[(size_t)NQ * DIM];    // normalized Q * log2e, fp16
__device__ __align__(16) __half g_Kh[(size_t)NKEY * DIM];  // NORMALIZED keys, fp16
__device__ __align__(16) __half g_Vt[(size_t)DIM * NKEY];  // raw keys^T [d][key], fp16
__device__ __align__(16) float  g_colsum[DIM];             // fp32 colsums of raw keys

// ---------------- helpers ----------------
__device__ __forceinline__ uint32_t smem_u32(const void* p) {
    uint32_t a;
    asm("{ .reg .u64 t; cvta.to.shared.u64 t, %1; cvt.u32.u64 %0, t; }" : "=r"(a) : "l"(p));
    return a;
}
__device__ __forceinline__ void ldsm4(uint32_t* r, uint32_t addr) {
    asm volatile("ldmatrix.sync.aligned.m8n8.x4.shared.b16 {%0,%1,%2,%3}, [%4];"
                 : "=r"(r[0]), "=r"(r[1]), "=r"(r[2]), "=r"(r[3]) : "r"(addr));
}
__device__ __forceinline__ void mma16816(float* d, const uint32_t* a, uint32_t b0, uint32_t b1) {
    asm volatile("mma.sync.aligned.m16n8k16.row.col.f32.f16.f16.f32 "
                 "{%0,%1,%2,%3}, {%4,%5,%6,%7}, {%8,%9}, {%0,%1,%2,%3};"
                 : "+f"(d[0]), "+f"(d[1]), "+f"(d[2]), "+f"(d[3])
                 : "r"(a[0]), "r"(a[1]), "r"(a[2]), "r"(a[3]), "r"(b0), "r"(b1));
}
__device__ __forceinline__ uint32_t packh(float hi, float lo) {
    uint32_t r; asm("cvt.rn.f16x2.f32 %0, %1, %2;" : "=r"(r) : "f"(hi), "f"(lo)); return r;
}
__device__ __forceinline__ void cp16(uint32_t saddr, const void* g) {
    asm volatile("cp.async.cg.shared.global [%0], [%1], 16;" :: "r"(saddr), "l"(g));
}
#define CP_COMMIT() asm volatile("cp.async.commit_group;" ::: "memory")
#define CP_WAIT0()  asm volatile("cp.async.wait_group 0;" ::: "memory")

// ---------------- prep kernels ----------------
__global__ void prep_q(const float* __restrict__ q) {
    int row = blockIdx.x * 8 + (threadIdx.x >> 5);
    int lane = threadIdx.x & 31;
    float4 v = ((const float4*)q)[(size_t)row * 32 + lane];
    float ss = v.x * v.x + v.y * v.y + v.z * v.z + v.w * v.w;
    #pragma unroll
    for (int o = 16; o > 0; o >>= 1) ss += __shfl_xor_sync(0xffffffffu, ss, o);
    // fold log2(e) so scores are in the exp2 domain
    float sc = 1.44269504f / fmaxf(sqrtf(ss), 1e-12f);
    __half2* dst = (__half2*)(g_Qh + (size_t)row * DIM + lane * 4);
    dst[0] = __float22half2_rn(make_float2(v.x * sc, v.y * sc));
    dst[1] = __float22half2_rn(make_float2(v.z * sc, v.w * sc));
}

__global__ void prep_k(const float* __restrict__ keys) {
    int row = blockIdx.x * 8 + (threadIdx.x >> 5);
    int lane = threadIdx.x & 31;
    float4 v = ((const float4*)keys)[(size_t)row * 32 + lane];
    float ss = v.x * v.x + v.y * v.y + v.z * v.z + v.w * v.w;
    #pragma unroll
    for (int o = 16; o > 0; o >>= 1) ss += __shfl_xor_sync(0xffffffffu, ss, o);
    float sc = 1.0f / fmaxf(sqrtf(ss), 1e-12f);
    __half2* dst = (__half2*)(g_Kh + (size_t)row * DIM + lane * 4);
    dst[0] = __float22half2_rn(make_float2(v.x * sc, v.y * sc));
    dst[1] = __float22half2_rn(make_float2(v.z * sc, v.w * sc));
    float xs[4] = {v.x, v.y, v.z, v.w};
    #pragma unroll
    for (int j = 0; j < 4; ++j)
        g_Vt[(size_t)(lane * 4 + j) * NKEY + row] = __float2half(xs[j]);
}

__global__ void prep_colsum(const float* __restrict__ keys) {
    __shared__ float red[256];
    int d = blockIdx.x;
    float s = 0.f;
    for (int k = threadIdx.x; k < NKEY; k += 256) s += keys[(size_t)k * DIM + d];
    red[threadIdx.x] = s;
    __syncthreads();
    for (int o = 128; o > 0; o >>= 1) {
        if ((int)threadIdx.x < o) red[threadIdx.x] += red[threadIdx.x + o];
        __syncthreads();
    }
    if (threadIdx.x == 0) g_colsum[d] = red[0];
}

// ---------------- main kernel ----------------
// smem: 2-stage pipeline { K tile 64x272B ; V^T tile 128x144B } + colsum
#define STG   35840      // bytes per stage (17408 K + 18432 V)
#define VOFF  17408
enum { CSOF = 2 * STG, SMTOT = 2 * STG + 512 };

__device__ __forceinline__ void issue_tile(uint32_t sb, int stg, int t, int tid) {
    uint32_t kb = sb + stg * STG;
    uint32_t vb = kb + VOFF;
    const __half* ks = g_Kh + (size_t)t * BK * DIM;
    const __half* vs = g_Vt + (size_t)t * BK;
    #pragma unroll
    for (int c = 0; c < 8; ++c) {
        int chunk = c * NTHREADS + tid;      // 1024 chunks = 64 rows x 16
        int r = chunk >> 4, o = chunk & 15;
        cp16(kb + r * SROWK + o * 16, ks + (size_t)r * DIM + o * 8);
    }
    #pragma unroll
    for (int c = 0; c < 8; ++c) {
        int chunk = c * NTHREADS + tid;      // 1024 chunks = 128 rows x 8
        int r = chunk >> 3, o = chunk & 7;
        cp16(vb + r * SROWV + o * 16, vs + (size_t)r * NKEY + o * 8);
    }
}

__global__ __launch_bounds__(NTHREADS, 3)
void mb_main(float* __restrict__ out) {
    extern __shared__ char sm[];
    const uint32_t sb = smem_u32(sm);
    const int tid = threadIdx.x, wid = tid >> 5, lane = tid & 31;

    if (tid < DIM) ((float*)(sm + CSOF))[tid] = g_colsum[tid];

    // Stage this CTA's 64-row Q tile into stage-0 K region (full 256B rows).
    {
        const __half* qs = g_Qh + (size_t)blockIdx.x * BM * DIM;
        #pragma unroll
        for (int c = 0; c < 8; ++c) {
            int chunk = c * NTHREADS + tid;  // 1024 chunks = 64 rows x 16
            int r = chunk >> 4, o = chunk & 15;
            *(uint4*)(sm + r * SROWK + o * 16) =
                *(const uint4*)(qs + (size_t)r * DIM + o * 8);
        }
    }
    __syncthreads();
    uint32_t qa[8][4];
    {
        int row = wid * 16 + (lane & 15);
        int colh = (lane >> 4) * 8;
        #pragma unroll
        for (int k = 0; k < 8; ++k)
            ldsm4(qa[k], sb + row * SROWK + (k * 16 + colh) * 2);
    }
    __syncthreads();   // Q fragments in regs before stage 0 is reused
    issue_tile(sb, 0, 0, tid); CP_COMMIT();

    float o_acc[16][4];
    #pragma unroll
    for (int j = 0; j < 16; ++j)
        #pragma unroll
        for (int c = 0; c < 4; ++c) o_acc[j][c] = 0.f;
    float zlo = 0.f, zhi = 0.f;

    const int bg = (lane >> 3) & 1, bc = (lane >> 4), br = lane & 7;
    const int krow = bg * 8 + br;

    for (int t = 0; t < NTILES; ++t) {
        int stg = t & 1;
        CP_WAIT0();        // tile t landed
        __syncthreads();   // visible; all warps done with tile t-1's buffer
        if (t + 1 < NTILES) issue_tile(sb, stg ^ 1, t + 1, tid);
        CP_COMMIT();       // overlaps with compute below

        uint32_t kb = sb + stg * STG;
        uint32_t vb = kb + VOFF;

        #pragma unroll
        for (int s = 0; s < 4; ++s) {
            // ---- S: 16 keys vs warp's 16 query rows, 2 chains, JIT ldsm ----
            float c0[4] = {0, 0, 0, 0}, c1[4] = {0, 0, 0, 0};
            #pragma unroll
            for (int k = 0; k < 8; ++k) {
                uint32_t kf[4];
                ldsm4(kf, kb + (uint32_t)((s * 16 + krow) * SROWK + (k * 16 + bc * 8) * 2));
                mma16816(c0, qa[k], kf[0], kf[2]);
                mma16816(c1, qa[k], kf[1], kf[3]);
            }
            // ---- exp2(s)-1, Z partials, pack PV A-fragment ----
            float p00 = exp2f(c0[0]) - 1.f, p01 = exp2f(c0[1]) - 1.f;
            float p02 = exp2f(c0[2]) - 1.f, p03 = exp2f(c0[3]) - 1.f;
            float p10 = exp2f(c1[0]) - 1.f, p11 = exp2f(c1[1]) - 1.f;
            float p12 = exp2f(c1[2]) - 1.f, p13 = exp2f(c1[3]) - 1.f;
            zlo += (p00 + p01) + (p10 + p11);
            zhi += (p02 + p03) + (p12 + p13);
            uint32_t pa[4];
            pa[0] = packh(p01, p00);
            pa[1] = packh(p03, p02);
            pa[2] = packh(p11, p10);
            pa[3] = packh(p13, p12);
            // ---- O += P @ V (16 chains, V fragments JIT) ----
            #pragma unroll
            for (int j = 0; j < 8; ++j) {
                uint32_t vf[4];
                ldsm4(vf, vb + (uint32_t)((j * 16 + krow) * SROWV + (s * 16 + bc * 8) * 2));
                mma16816(o_acc[2 * j],     pa, vf[0], vf[2]);
                mma16816(o_acc[2 * j + 1], pa, vf[1], vf[3]);
            }
        }
    }

    // ---- epilogue: Z warp-reduce, add colsum, normalize, write ----
    zlo += __shfl_xor_sync(0xffffffffu, zlo, 1);
    zlo += __shfl_xor_sync(0xffffffffu, zlo, 2);
    zhi += __shfl_xor_sync(0xffffffffu, zhi, 1);
    zhi += __shfl_xor_sync(0xffffffffu, zhi, 2);
    float invZlo = 1.0f / ((float)NKEY + zlo);
    float invZhi = 1.0f / ((float)NKEY + zhi);

    const float* cs = (const float*)(sm + CSOF);
    size_t row0 = (size_t)blockIdx.x * BM + wid * 16 + (lane >> 2);
    int col0 = (lane & 3) * 2;
    #pragma unroll
    for (int j = 0; j < 16; ++j) {
        int c = j * 8 + col0;
        float2 v0 = make_float2((cs[c] + o_acc[j][0]) * invZlo,
                                (cs[c + 1] + o_acc[j][1]) * invZlo);
        float2 v1 = make_float2((cs[c] + o_acc[j][2]) * invZhi,
                                (cs[c + 1] + o_acc[j][3]) * invZhi);
        *(float2*)&out[row0 * DIM + c] = v0;
        *(float2*)&out[(row0 + 8) * DIM + c] = v1;
    }
}

// ---------------- launch ----------------
extern "C" void kernel_launch(void* const* d_in, const int* in_sizes, int n_in,
                              void* d_out, int out_size) {
    const float* queries = (const float*)d_in[0];
    const float* keys    = (const float*)d_in[1];
    float* out = (float*)d_out;
    int N = in_sizes[0] / DIM;

    prep_q<<<N / 8, 256>>>(queries);
    prep_k<<<NKEY / 8, 256>>>(keys);
    prep_colsum<<<DIM, 256>>>(keys);

    cudaFuncSetAttribute(mb_main, cudaFuncAttributeMaxDynamicSharedMemorySize, SMTOT);
    mb_main<<<N / BM, NTHREADS, SMTOT>>>(out);
}

// round 12
// speedup vs baseline: 1.0527x; 1.0527x over previous
#include <cuda_runtime.h>
#include <cuda_fp16.h>
#include <cstdint>

// out = softmax(normalize(Q)@normalize(K)^T) @ K,  N=65536, K=4096, D=128, fp32
// fp16 mma.sync dataflow (proven, rel_err 9.5e-5):
//   S  = Qn @ Kn^T  (non-trans ldsm4 on [key][d] tile)   [Qn prescaled by log2e]
//   O += (ex2(S)-1) @ V  (non-trans ldsm4 on V^T [d][key] tile)
//   out = (colsum(V) + O) / Z
// R11: warp-staggered s-loop (warp w does s=(si+w)&3) so tensor/MUFU phases of
//      different warps overlap instead of aligning; ex2.approx asm (1 MUFU).

#define NQ 65536
#define NKEY 4096
#define DIM 128
#define BM 64
#define BK 64
#define NTILES (NKEY / BK)
#define NTHREADS 128
#define SROWK 272         // K tile row stride bytes (128 fp16 + 16B pad)
#define SROWV 144         // V^T tile row stride bytes (64 fp16 + 16B pad)

__device__ __align__(16) __half g_Qh[(size_t)NQ * DIM];    // normalized Q * log2e, fp16
__device__ __align__(16) __half g_Kh[(size_t)NKEY * DIM];  // NORMALIZED keys, fp16
__device__ __align__(16) __half g_Vt[(size_t)DIM * NKEY];  // raw keys^T [d][key], fp16
__device__ __align__(16) float  g_colsum[DIM];             // fp32 colsums of raw keys

// ---------------- helpers ----------------
__device__ __forceinline__ uint32_t smem_u32(const void* p) {
    uint32_t a;
    asm("{ .reg .u64 t; cvta.to.shared.u64 t, %1; cvt.u32.u64 %0, t; }" : "=r"(a) : "l"(p));
    return a;
}
__device__ __forceinline__ float ex2(float x) {
    float y; asm("ex2.approx.f32 %0, %1;" : "=f"(y) : "f"(x)); return y;
}
__device__ __forceinline__ void ldsm4(uint32_t* r, uint32_t addr) {
    asm volatile("ldmatrix.sync.aligned.m8n8.x4.shared.b16 {%0,%1,%2,%3}, [%4];"
                 : "=r"(r[0]), "=r"(r[1]), "=r"(r[2]), "=r"(r[3]) : "r"(addr));
}
__device__ __forceinline__ void mma16816(float* d, const uint32_t* a, uint32_t b0, uint32_t b1) {
    asm volatile("mma.sync.aligned.m16n8k16.row.col.f32.f16.f16.f32 "
                 "{%0,%1,%2,%3}, {%4,%5,%6,%7}, {%8,%9}, {%0,%1,%2,%3};"
                 : "+f"(d[0]), "+f"(d[1]), "+f"(d[2]), "+f"(d[3])
                 : "r"(a[0]), "r"(a[1]), "r"(a[2]), "r"(a[3]), "r"(b0), "r"(b1));
}
__device__ __forceinline__ uint32_t packh(float hi, float lo) {
    uint32_t r; asm("cvt.rn.f16x2.f32 %0, %1, %2;" : "=r"(r) : "f"(hi), "f"(lo)); return r;
}
__device__ __forceinline__ void cp16(uint32_t saddr, const void* g) {
    asm volatile("cp.async.cg.shared.global [%0], [%1], 16;" :: "r"(saddr), "l"(g));
}
#define CP_COMMIT() asm volatile("cp.async.commit_group;" ::: "memory")
#define CP_WAIT1()  asm volatile("cp.async.wait_group 1;" ::: "memory")

// ---------------- prep kernels ----------------
__global__ void prep_q(const float* __restrict__ q) {
    int row = blockIdx.x * 8 + (threadIdx.x >> 5);
    int lane = threadIdx.x & 31;
    float4 v = ((const float4*)q)[(size_t)row * 32 + lane];
    float ss = v.x * v.x + v.y * v.y + v.z * v.z + v.w * v.w;
    #pragma unroll
    for (int o = 16; o > 0; o >>= 1) ss += __shfl_xor_sync(0xffffffffu, ss, o);
    float sc = 1.44269504f / fmaxf(sqrtf(ss), 1e-12f);   // fold log2(e)
    __half2* dst = (__half2*)(g_Qh + (size_t)row * DIM + lane * 4);
    dst[0] = __float22half2_rn(make_float2(v.x * sc, v.y * sc));
    dst[1] = __float22half2_rn(make_float2(v.z * sc, v.w * sc));
}

__global__ void prep_k(const float* __restrict__ keys) {
    int row = blockIdx.x * 8 + (threadIdx.x >> 5);
    int lane = threadIdx.x & 31;
    float4 v = ((const float4*)keys)[(size_t)row * 32 + lane];
    float ss = v.x * v.x + v.y * v.y + v.z * v.z + v.w * v.w;
    #pragma unroll
    for (int o = 16; o > 0; o >>= 1) ss += __shfl_xor_sync(0xffffffffu, ss, o);
    float sc = 1.0f / fmaxf(sqrtf(ss), 1e-12f);
    __half2* dst = (__half2*)(g_Kh + (size_t)row * DIM + lane * 4);
    dst[0] = __float22half2_rn(make_float2(v.x * sc, v.y * sc));
    dst[1] = __float22half2_rn(make_float2(v.z * sc, v.w * sc));
    float xs[4] = {v.x, v.y, v.z, v.w};
    #pragma unroll
    for (int j = 0; j < 4; ++j)
        g_Vt[(size_t)(lane * 4 + j) * NKEY + row] = __float2half(xs[j]);
}

__global__ void prep_colsum(const float* __restrict__ keys) {
    __shared__ float red[256];
    int d = blockIdx.x;
    float s = 0.f;
    for (int k = threadIdx.x; k < NKEY; k += 256) s += keys[(size_t)k * DIM + d];
    red[threadIdx.x] = s;
    __syncthreads();
    for (int o = 128; o > 0; o >>= 1) {
        if ((int)threadIdx.x < o) red[threadIdx.x] += red[threadIdx.x + o];
        __syncthreads();
    }
    if (threadIdx.x == 0) g_colsum[d] = red[0];
}

// ---------------- main kernel ----------------
// smem: 3-stage pipeline { K tile 64x272B ; V^T tile 128x144B } + colsum
#define STG   35840      // bytes per stage (17408 K + 18432 V)
#define VOFF  17408
enum { CSOF = 3 * STG, SMTOT = 3 * STG + 512 };

__device__ __forceinline__ void issue_tile(uint32_t sb, int stg, int t, int tid) {
    uint32_t kb = sb + stg * STG;
    uint32_t vb = kb + VOFF;
    const __half* ks = g_Kh + (size_t)t * BK * DIM;
    const __half* vs = g_Vt + (size_t)t * BK;
    #pragma unroll
    for (int c = 0; c < 8; ++c) {
        int chunk = c * NTHREADS + tid;      // 1024 chunks = 64 rows x 16
        int r = chunk >> 4, o = chunk & 15;
        cp16(kb + r * SROWK + o * 16, ks + (size_t)r * DIM + o * 8);
    }
    #pragma unroll
    for (int c = 0; c < 8; ++c) {
        int chunk = c * NTHREADS + tid;      // 1024 chunks = 128 rows x 8
        int r = chunk >> 3, o = chunk & 7;
        cp16(vb + r * SROWV + o * 16, vs + (size_t)r * NKEY + o * 8);
    }
}

__global__ __launch_bounds__(NTHREADS, 2)
void mb_main(float* __restrict__ out) {
    extern __shared__ char sm[];
    const uint32_t sb = smem_u32(sm);
    const int tid = threadIdx.x, wid = tid >> 5, lane = tid & 31;

    if (tid < DIM) ((float*)(sm + CSOF))[tid] = g_colsum[tid];

    // Stage this CTA's 64-row Q tile into stage-2 K region (full 256B rows).
    {
        const __half* qs = g_Qh + (size_t)blockIdx.x * BM * DIM;
        #pragma unroll
        for (int c = 0; c < 8; ++c) {
            int chunk = c * NTHREADS + tid;  // 1024 chunks = 64 rows x 16
            int r = chunk >> 4, o = chunk & 15;
            *(uint4*)(sm + 2 * STG + r * SROWK + o * 16) =
                *(const uint4*)(qs + (size_t)r * DIM + o * 8);
        }
    }
    // Start the pipeline while Q settles: tiles 0,1 into stages 0,1.
    issue_tile(sb, 0, 0, tid); CP_COMMIT();
    issue_tile(sb, 1, 1, tid); CP_COMMIT();
    __syncthreads();

    uint32_t qa[8][4];
    {
        int row = wid * 16 + (lane & 15);
        int colh = (lane >> 4) * 8;
        #pragma unroll
        for (int k = 0; k < 8; ++k)
            ldsm4(qa[k], sb + 2 * STG + row * SROWK + (k * 16 + colh) * 2);
    }

    float o_acc[16][4];
    #pragma unroll
    for (int j = 0; j < 16; ++j)
        #pragma unroll
        for (int c = 0; c < 4; ++c) o_acc[j][c] = 0.f;
    float zlo = 0.f, zhi = 0.f;

    const int bg = (lane >> 3) & 1, bc = (lane >> 4), br = lane & 7;
    const int krow = bg * 8 + br;

    int stg = 0;       // stage holding tile t
    for (int t = 0; t < NTILES; ++t) {
        CP_WAIT1();        // tile t landed (t+1 may still be in flight)
        __syncthreads();   // visible to all warps; tile t-1 compute done CTA-wide

        // Prefetch tile t+2 into the stage freed by tile t-1 (overlaps compute).
        int wstg = stg - 1; if (wstg < 0) wstg = 2;
        if (t + 2 < NTILES) issue_tile(sb, wstg, t + 2, tid);
        CP_COMMIT();

        uint32_t kb = sb + stg * STG;
        uint32_t vb = kb + VOFF;

        // Warp-staggered s-loop: warp w starts at subtile w (mod 4), so the
        // MMA burst of one warp overlaps the MUFU/pack phase of another.
        #pragma unroll
        for (int si = 0; si < 4; ++si) {
            const int s = (si + wid) & 3;
            // ---- batched K-fragment loads, 4 S accumulator chains ----
            uint32_t kf[8][4];
            #pragma unroll
            for (int k = 0; k < 8; ++k)
                ldsm4(kf[k], kb + (uint32_t)((s * 16 + krow) * SROWK + (k * 16 + bc * 8) * 2));
            float c0[4] = {0,0,0,0}, c1[4] = {0,0,0,0};
            float c2[4] = {0,0,0,0}, c3[4] = {0,0,0,0};
            #pragma unroll
            for (int k = 0; k < 8; k += 2) {
                mma16816(c0, qa[k],     kf[k][0],     kf[k][2]);
                mma16816(c1, qa[k],     kf[k][1],     kf[k][3]);
                mma16816(c2, qa[k + 1], kf[k + 1][0], kf[k + 1][2]);
                mma16816(c3, qa[k + 1], kf[k + 1][1], kf[k + 1][3]);
            }
            // ---- ex2(s)-1 (bare MUFU), Z partials, pack PV A-fragment ----
            float p00 = ex2(c0[0] + c2[0]) - 1.f, p01 = ex2(c0[1] + c2[1]) - 1.f;
            float p02 = ex2(c0[2] + c2[2]) - 1.f, p03 = ex2(c0[3] + c2[3]) - 1.f;
            float p10 = ex2(c1[0] + c3[0]) - 1.f, p11 = ex2(c1[1] + c3[1]) - 1.f;
            float p12 = ex2(c1[2] + c3[2]) - 1.f, p13 = ex2(c1[3] + c3[3]) - 1.f;
            zlo += (p00 + p01) + (p10 + p11);
            zhi += (p02 + p03) + (p12 + p13);
            uint32_t pa[4];
            pa[0] = packh(p01, p00);
            pa[1] = packh(p03, p02);
            pa[2] = packh(p11, p10);
            pa[3] = packh(p13, p12);
            // ---- O += P @ V (16 chains, V fragments JIT) ----
            #pragma unroll
            for (int j = 0; j < 8; ++j) {
                uint32_t vf[4];
                ldsm4(vf, vb + (uint32_t)((j * 16 + krow) * SROWV + (s * 16 + bc * 8) * 2));
                mma16816(o_acc[2 * j],     pa, vf[0], vf[2]);
                mma16816(o_acc[2 * j + 1], pa, vf[1], vf[3]);
            }
        }
        if (++stg == 3) stg = 0;
    }

    // ---- epilogue: Z warp-reduce, add colsum, normalize, write ----
    zlo += __shfl_xor_sync(0xffffffffu, zlo, 1);
    zlo += __shfl_xor_sync(0xffffffffu, zlo, 2);
    zhi += __shfl_xor_sync(0xffffffffu, zhi, 1);
    zhi += __shfl_xor_sync(0xffffffffu, zhi, 2);
    float invZlo = 1.0f / ((float)NKEY + zlo);
    float invZhi = 1.0f / ((float)NKEY + zhi);

    const float* cs = (const float*)(sm + CSOF);
    size_t row0 = (size_t)blockIdx.x * BM + wid * 16 + (lane >> 2);
    int col0 = (lane & 3) * 2;
    #pragma unroll
    for (int j = 0; j < 16; ++j) {
        int c = j * 8 + col0;
        float2 v0 = make_float2((cs[c] + o_acc[j][0]) * invZlo,
                                (cs[c + 1] + o_acc[j][1]) * invZlo);
        float2 v1 = make_float2((cs[c] + o_acc[j][2]) * invZhi,
                                (cs[c + 1] + o_acc[j][3]) * invZhi);
        *(float2*)&out[row0 * DIM + c] = v0;
        *(float2*)&out[(row0 + 8) * DIM + c] = v1;
    }
}

// ---------------- launch ----------------
extern "C" void kernel_launch(void* const* d_in, const int* in_sizes, int n_in,
                              void* d_out, int out_size) {
    const float* queries = (const float*)d_in[0];
    const float* keys    = (const float*)d_in[1];
    float* out = (float*)d_out;
    int N = in_sizes[0] / DIM;

    prep_q<<<N / 8, 256>>>(queries);
    prep_k<<<NKEY / 8, 256>>>(keys);
    prep_colsum<<<DIM, 256>>>(keys);

    cudaFuncSetAttribute(mb_main, cudaFuncAttributeMaxDynamicSharedMemorySize, SMTOT);
    mb_main<<<N / BM, NTHREADS, SMTOT>>>(out);
}

// round 13
// speedup vs baseline: 1.0713x; 1.0176x over previous
#include <cuda_runtime.h>
#include <cuda_fp16.h>
#include <cstdint>

// out = softmax(normalize(Q)@normalize(K)^T) @ K,  N=65536, K=4096, D=128, fp32
// fp16 mma.sync dataflow (proven, rel_err 9.5e-5):
//   S  = Qn @ Kn^T  (non-trans ldsm4 on [key][d] tile)   [Qn prescaled by log2e]
//   O += (ex2(S)-1) @ V  (non-trans ldsm4 on V^T [d][key] tile)
//   out = (colsum(V) + O) / Z
// R12: M_warp = 32 (2 m16 row-blocks per warp) — each B-fragment ldsm feeds
//      4 MMAs instead of 2, halving smem traffic per MMA and doubling the
//      tensor-busy fraction of each warp's serial budget.

#define NQ 65536
#define NKEY 4096
#define DIM 128
#define BM 128            // 4 warps x 32 rows
#define BK 64
#define NTILES (NKEY / BK)
#define NTHREADS 128
#define SROWK 272         // K tile row stride bytes (128 fp16 + 16B pad)
#define SROWV 144         // V^T tile row stride bytes (64 fp16 + 16B pad)

__device__ __align__(16) __half g_Qh[(size_t)NQ * DIM];    // normalized Q * log2e, fp16
__device__ __align__(16) __half g_Kh[(size_t)NKEY * DIM];  // NORMALIZED keys, fp16
__device__ __align__(16) __half g_Vt[(size_t)DIM * NKEY];  // raw keys^T [d][key], fp16
__device__ __align__(16) float  g_colsum[DIM];             // fp32 colsums of raw keys

// ---------------- helpers ----------------
__device__ __forceinline__ uint32_t smem_u32(const void* p) {
    uint32_t a;
    asm("{ .reg .u64 t; cvta.to.shared.u64 t, %1; cvt.u32.u64 %0, t; }" : "=r"(a) : "l"(p));
    return a;
}
__device__ __forceinline__ float ex2(float x) {
    float y; asm("ex2.approx.f32 %0, %1;" : "=f"(y) : "f"(x)); return y;
}
__device__ __forceinline__ void ldsm4(uint32_t* r, uint32_t addr) {
    asm volatile("ldmatrix.sync.aligned.m8n8.x4.shared.b16 {%0,%1,%2,%3}, [%4];"
                 : "=r"(r[0]), "=r"(r[1]), "=r"(r[2]), "=r"(r[3]) : "r"(addr));
}
__device__ __forceinline__ void mma16816(float* d, const uint32_t* a, uint32_t b0, uint32_t b1) {
    asm volatile("mma.sync.aligned.m16n8k16.row.col.f32.f16.f16.f32 "
                 "{%0,%1,%2,%3}, {%4,%5,%6,%7}, {%8,%9}, {%0,%1,%2,%3};"
                 : "+f"(d[0]), "+f"(d[1]), "+f"(d[2]), "+f"(d[3])
                 : "r"(a[0]), "r"(a[1]), "r"(a[2]), "r"(a[3]), "r"(b0), "r"(b1));
}
__device__ __forceinline__ uint32_t packh(float hi, float lo) {
    uint32_t r; asm("cvt.rn.f16x2.f32 %0, %1, %2;" : "=r"(r) : "f"(hi), "f"(lo)); return r;
}
__device__ __forceinline__ void cp16(uint32_t saddr, const void* g) {
    asm volatile("cp.async.cg.shared.global [%0], [%1], 16;" :: "r"(saddr), "l"(g));
}
#define CP_COMMIT() asm volatile("cp.async.commit_group;" ::: "memory")
#define CP_WAIT0()  asm volatile("cp.async.wait_group 0;" ::: "memory")

// ---------------- prep kernels ----------------
__global__ void prep_q(const float* __restrict__ q) {
    int row = blockIdx.x * 8 + (threadIdx.x >> 5);
    int lane = threadIdx.x & 31;
    float4 v = ((const float4*)q)[(size_t)row * 32 + lane];
    float ss = v.x * v.x + v.y * v.y + v.z * v.z + v.w * v.w;
    #pragma unroll
    for (int o = 16; o > 0; o >>= 1) ss += __shfl_xor_sync(0xffffffffu, ss, o);
    float sc = 1.44269504f / fmaxf(sqrtf(ss), 1e-12f);   // fold log2(e)
    __half2* dst = (__half2*)(g_Qh + (size_t)row * DIM + lane * 4);
    dst[0] = __float22half2_rn(make_float2(v.x * sc, v.y * sc));
    dst[1] = __float22half2_rn(make_float2(v.z * sc, v.w * sc));
}

__global__ void prep_k(const float* __restrict__ keys) {
    int row = blockIdx.x * 8 + (threadIdx.x >> 5);
    int lane = threadIdx.x & 31;
    float4 v = ((const float4*)keys)[(size_t)row * 32 + lane];
    float ss = v.x * v.x + v.y * v.y + v.z * v.z + v.w * v.w;
    #pragma unroll
    for (int o = 16; o > 0; o >>= 1) ss += __shfl_xor_sync(0xffffffffu, ss, o);
    float sc = 1.0f / fmaxf(sqrtf(ss), 1e-12f);
    __half2* dst = (__half2*)(g_Kh + (size_t)row * DIM + lane * 4);
    dst[0] = __float22half2_rn(make_float2(v.x * sc, v.y * sc));
    dst[1] = __float22half2_rn(make_float2(v.z * sc, v.w * sc));
    float xs[4] = {v.x, v.y, v.z, v.w};
    #pragma unroll
    for (int j = 0; j < 4; ++j)
        g_Vt[(size_t)(lane * 4 + j) * NKEY + row] = __float2half(xs[j]);
}

__global__ void prep_colsum(const float* __restrict__ keys) {
    __shared__ float red[256];
    int d = blockIdx.x;
    float s = 0.f;
    for (int k = threadIdx.x; k < NKEY; k += 256) s += keys[(size_t)k * DIM + d];
    red[threadIdx.x] = s;
    __syncthreads();
    for (int o = 128; o > 0; o >>= 1) {
        if ((int)threadIdx.x < o) red[threadIdx.x] += red[threadIdx.x + o];
        __syncthreads();
    }
    if (threadIdx.x == 0) g_colsum[d] = red[0];
}

// ---------------- main kernel ----------------
// smem: 2-stage pipeline { K tile 64x272B ; V^T tile 128x144B } + colsum
#define STG   35840      // bytes per stage (17408 K + 18432 V)
#define VOFF  17408
enum { CSOF = 2 * STG, SMTOT = 2 * STG + 512 };

__device__ __forceinline__ void issue_tile(uint32_t sb, int stg, int t, int tid) {
    uint32_t kb = sb + stg * STG;
    uint32_t vb = kb + VOFF;
    const __half* ks = g_Kh + (size_t)t * BK * DIM;
    const __half* vs = g_Vt + (size_t)t * BK;
    #pragma unroll
    for (int c = 0; c < 8; ++c) {
        int chunk = c * NTHREADS + tid;      // 1024 chunks = 64 rows x 16
        int r = chunk >> 4, o = chunk & 15;
        cp16(kb + r * SROWK + o * 16, ks + (size_t)r * DIM + o * 8);
    }
    #pragma unroll
    for (int c = 0; c < 8; ++c) {
        int chunk = c * NTHREADS + tid;      // 1024 chunks = 128 rows x 8
        int r = chunk >> 3, o = chunk & 7;
        cp16(vb + r * SROWV + o * 16, vs + (size_t)r * NKEY + o * 8);
    }
}

__global__ __launch_bounds__(NTHREADS, 2)
void mb_main(float* __restrict__ out) {
    extern __shared__ char sm[];
    const uint32_t sb = smem_u32(sm);
    const int tid = threadIdx.x, wid = tid >> 5, lane = tid & 31;

    if (tid < DIM) ((float*)(sm + CSOF))[tid] = g_colsum[tid];

    // Stage this CTA's 128-row Q tile into stage-0 region (128*272=34816 <= STG).
    {
        const __half* qs = g_Qh + (size_t)blockIdx.x * BM * DIM;
        #pragma unroll
        for (int c = 0; c < 16; ++c) {
            int chunk = c * NTHREADS + tid;  // 2048 chunks = 128 rows x 16
            int r = chunk >> 4, o = chunk & 15;
            *(uint4*)(sm + r * SROWK + o * 16) =
                *(const uint4*)(qs + (size_t)r * DIM + o * 8);
        }
    }
    __syncthreads();
    // Q A-fragments: 2 row-blocks of m16 per warp (warp owns 32 rows).
    uint32_t qa[2][8][4];
    {
        int colh = (lane >> 4) * 8;
        #pragma unroll
        for (int rb = 0; rb < 2; ++rb) {
            int row = wid * 32 + rb * 16 + (lane & 15);
            #pragma unroll
            for (int k = 0; k < 8; ++k)
                ldsm4(qa[rb][k], sb + row * SROWK + (k * 16 + colh) * 2);
        }
    }
    __syncthreads();   // Q fragments in regs before stage 0 is reused
    issue_tile(sb, 0, 0, tid); CP_COMMIT();

    float o_acc[2][16][4];
    #pragma unroll
    for (int rb = 0; rb < 2; ++rb)
        #pragma unroll
        for (int j = 0; j < 16; ++j)
            #pragma unroll
            for (int c = 0; c < 4; ++c) o_acc[rb][j][c] = 0.f;
    float zlo[2] = {0.f, 0.f}, zhi[2] = {0.f, 0.f};

    const int bg = (lane >> 3) & 1, bc = (lane >> 4), br = lane & 7;
    const int krow = bg * 8 + br;

    for (int t = 0; t < NTILES; ++t) {
        int stg = t & 1;
        CP_WAIT0();        // tile t landed
        __syncthreads();   // visible; all warps done with the other buffer
        if (t + 1 < NTILES) issue_tile(sb, stg ^ 1, t + 1, tid);
        CP_COMMIT();       // overlaps with compute below

        uint32_t kb = sb + stg * STG;
        uint32_t vb = kb + VOFF;

        #pragma unroll
        for (int s = 0; s < 4; ++s) {
            // ---- S: 16 keys vs warp's 32 query rows; each kf feeds 4 MMAs ----
            float c0[2][4] = {{0,0,0,0},{0,0,0,0}};
            float c1[2][4] = {{0,0,0,0},{0,0,0,0}};
            #pragma unroll
            for (int k = 0; k < 8; ++k) {
                uint32_t kf[4];
                ldsm4(kf, kb + (uint32_t)((s * 16 + krow) * SROWK + (k * 16 + bc * 8) * 2));
                mma16816(c0[0], qa[0][k], kf[0], kf[2]);
                mma16816(c1[0], qa[0][k], kf[1], kf[3]);
                mma16816(c0[1], qa[1][k], kf[0], kf[2]);
                mma16816(c1[1], qa[1][k], kf[1], kf[3]);
            }
            // ---- ex2(s)-1, Z partials, pack PV A-fragments (both row-blocks) ----
            uint32_t pa[2][4];
            #pragma unroll
            for (int rb = 0; rb < 2; ++rb) {
                float p00 = ex2(c0[rb][0]) - 1.f, p01 = ex2(c0[rb][1]) - 1.f;
                float p02 = ex2(c0[rb][2]) - 1.f, p03 = ex2(c0[rb][3]) - 1.f;
                float p10 = ex2(c1[rb][0]) - 1.f, p11 = ex2(c1[rb][1]) - 1.f;
                float p12 = ex2(c1[rb][2]) - 1.f, p13 = ex2(c1[rb][3]) - 1.f;
                zlo[rb] += (p00 + p01) + (p10 + p11);
                zhi[rb] += (p02 + p03) + (p12 + p13);
                pa[rb][0] = packh(p01, p00);
                pa[rb][1] = packh(p03, p02);
                pa[rb][2] = packh(p11, p10);
                pa[rb][3] = packh(p13, p12);
            }
            // ---- O += P @ V; each vf feeds 4 MMAs ----
            #pragma unroll
            for (int j = 0; j < 8; ++j) {
                uint32_t vf[4];
                ldsm4(vf, vb + (uint32_t)((j * 16 + krow) * SROWV + (s * 16 + bc * 8) * 2));
                mma16816(o_acc[0][2 * j],     pa[0], vf[0], vf[2]);
                mma16816(o_acc[0][2 * j + 1], pa[0], vf[1], vf[3]);
                mma16816(o_acc[1][2 * j],     pa[1], vf[0], vf[2]);
                mma16816(o_acc[1][2 * j + 1], pa[1], vf[1], vf[3]);
            }
        }
    }

    // ---- epilogue: Z warp-reduce, add colsum, normalize, write (2 row-blocks) ----
    const float* cs = (const float*)(sm + CSOF);
    int col0 = (lane & 3) * 2;
    #pragma unroll
    for (int rb = 0; rb < 2; ++rb) {
        float zl = zlo[rb], zh = zhi[rb];
        zl += __shfl_xor_sync(0xffffffffu, zl, 1);
        zl += __shfl_xor_sync(0xffffffffu, zl, 2);
        zh += __shfl_xor_sync(0xffffffffu, zh, 1);
        zh += __shfl_xor_sync(0xffffffffu, zh, 2);
        float invZlo = 1.0f / ((float)NKEY + zl);
        float invZhi = 1.0f / ((float)NKEY + zh);
        size_t row0 = (size_t)blockIdx.x * BM + wid * 32 + rb * 16 + (lane >> 2);
        #pragma unroll
        for (int j = 0; j < 16; ++j) {
            int c = j * 8 + col0;
            float2 v0 = make_float2((cs[c] + o_acc[rb][j][0]) * invZlo,
                                    (cs[c + 1] + o_acc[rb][j][1]) * invZlo);
            float2 v1 = make_float2((cs[c] + o_acc[rb][j][2]) * invZhi,
                                    (cs[c + 1] + o_acc[rb][j][3]) * invZhi);
            *(float2*)&out[row0 * DIM + c] = v0;
            *(float2*)&out[(row0 + 8) * DIM + c] = v1;
        }
    }
}

// ---------------- launch ----------------
extern "C" void kernel_launch(void* const* d_in, const int* in_sizes, int n_in,
                              void* d_out, int out_size) {
    const float* queries = (const float*)d_in[0];
    const float* keys    = (const float*)d_in[1];
    float* out = (float*)d_out;
    int N = in_sizes[0] / DIM;

    prep_q<<<N / 8, 256>>>(queries);
    prep_k<<<NKEY / 8, 256>>>(keys);
    prep_colsum<<<DIM, 256>>>(keys);

    cudaFuncSetAttribute(mb_main, cudaFuncAttributeMaxDynamicSharedMemorySize, SMTOT);
    mb_main<<<N / BM, NTHREADS, SMTOT>>>(out);
}

// round 14
// speedup vs baseline: 1.0968x; 1.0239x over previous
#include <cuda_runtime.h>
#include <cuda_fp16.h>
#include <cstdint>

// out = softmax(normalize(Q)@normalize(K)^T) @ K,  N=65536, K=4096, D=128, fp32
// fp16 mma.sync dataflow (proven, rel_err 9.5e-5), R12 mainloop (M_warp=32).
// R13: split-K x4 — 2048 work units of 16 key-tiles each so the CTA wave
//      quantization loss drops 13.5% -> 1.1%. Partials are exactly additive:
//      out = (colsum + sum_sp (P-1)@V_sp) / (NKEY + sum_sp Z_sp).

#define NQ 65536
#define NKEY 4096
#define DIM 128
#define BM 128            // 4 warps x 32 rows
#define BK 64
#define NSPLIT 4
#define TPS (NKEY / BK / NSPLIT)   // 16 tiles per split
#define NTHREADS 128
#define SROWK 272
#define SROWV 144

__device__ __align__(16) __half g_Qh[(size_t)NQ * DIM];    // normalized Q * log2e
__device__ __align__(16) __half g_Kh[(size_t)NKEY * DIM];  // NORMALIZED keys
__device__ __align__(16) __half g_Vt[(size_t)DIM * NKEY];  // raw keys^T [d][key]
__device__ __align__(16) float  g_colsum[DIM];
__device__ __align__(16) float  g_Op[NSPLIT][(size_t)NQ * DIM];  // partial (P-1)@V
__device__ __align__(16) float  g_Zp[NSPLIT][NQ];                // partial Z

// ---------------- helpers ----------------
__device__ __forceinline__ uint32_t smem_u32(const void* p) {
    uint32_t a;
    asm("{ .reg .u64 t; cvta.to.shared.u64 t, %1; cvt.u32.u64 %0, t; }" : "=r"(a) : "l"(p));
    return a;
}
__device__ __forceinline__ float ex2(float x) {
    float y; asm("ex2.approx.f32 %0, %1;" : "=f"(y) : "f"(x)); return y;
}
__device__ __forceinline__ void ldsm4(uint32_t* r, uint32_t addr) {
    asm volatile("ldmatrix.sync.aligned.m8n8.x4.shared.b16 {%0,%1,%2,%3}, [%4];"
                 : "=r"(r[0]), "=r"(r[1]), "=r"(r[2]), "=r"(r[3]) : "r"(addr));
}
__device__ __forceinline__ void mma16816(float* d, const uint32_t* a, uint32_t b0, uint32_t b1) {
    asm volatile("mma.sync.aligned.m16n8k16.row.col.f32.f16.f16.f32 "
                 "{%0,%1,%2,%3}, {%4,%5,%6,%7}, {%8,%9}, {%0,%1,%2,%3};"
                 : "+f"(d[0]), "+f"(d[1]), "+f"(d[2]), "+f"(d[3])
                 : "r"(a[0]), "r"(a[1]), "r"(a[2]), "r"(a[3]), "r"(b0), "r"(b1));
}
__device__ __forceinline__ uint32_t packh(float hi, float lo) {
    uint32_t r; asm("cvt.rn.f16x2.f32 %0, %1, %2;" : "=r"(r) : "f"(hi), "f"(lo)); return r;
}
__device__ __forceinline__ void cp16(uint32_t saddr, const void* g) {
    asm volatile("cp.async.cg.shared.global [%0], [%1], 16;" :: "r"(saddr), "l"(g));
}
#define CP_COMMIT() asm volatile("cp.async.commit_group;" ::: "memory")
#define CP_WAIT0()  asm volatile("cp.async.wait_group 0;" ::: "memory")

// ---------------- prep kernels ----------------
__global__ void prep_q(const float* __restrict__ q) {
    int row = blockIdx.x * 8 + (threadIdx.x >> 5);
    int lane = threadIdx.x & 31;
    float4 v = ((const float4*)q)[(size_t)row * 32 + lane];
    float ss = v.x * v.x + v.y * v.y + v.z * v.z + v.w * v.w;
    #pragma unroll
    for (int o = 16; o > 0; o >>= 1) ss += __shfl_xor_sync(0xffffffffu, ss, o);
    float sc = 1.44269504f / fmaxf(sqrtf(ss), 1e-12f);   // fold log2(e)
    __half2* dst = (__half2*)(g_Qh + (size_t)row * DIM + lane * 4);
    dst[0] = __float22half2_rn(make_float2(v.x * sc, v.y * sc));
    dst[1] = __float22half2_rn(make_float2(v.z * sc, v.w * sc));
}

__global__ void prep_k(const float* __restrict__ keys) {
    int row = blockIdx.x * 8 + (threadIdx.x >> 5);
    int lane = threadIdx.x & 31;
    float4 v = ((const float4*)keys)[(size_t)row * 32 + lane];
    float ss = v.x * v.x + v.y * v.y + v.z * v.z + v.w * v.w;
    #pragma unroll
    for (int o = 16; o > 0; o >>= 1) ss += __shfl_xor_sync(0xffffffffu, ss, o);
    float sc = 1.0f / fmaxf(sqrtf(ss), 1e-12f);
    __half2* dst = (__half2*)(g_Kh + (size_t)row * DIM + lane * 4);
    dst[0] = __float22half2_rn(make_float2(v.x * sc, v.y * sc));
    dst[1] = __float22half2_rn(make_float2(v.z * sc, v.w * sc));
    float xs[4] = {v.x, v.y, v.z, v.w};
    #pragma unroll
    for (int j = 0; j < 4; ++j)
        g_Vt[(size_t)(lane * 4 + j) * NKEY + row] = __float2half(xs[j]);
}

__global__ void prep_colsum(const float* __restrict__ keys) {
    __shared__ float red[256];
    int d = blockIdx.x;
    float s = 0.f;
    for (int k = threadIdx.x; k < NKEY; k += 256) s += keys[(size_t)k * DIM + d];
    red[threadIdx.x] = s;
    __syncthreads();
    for (int o = 128; o > 0; o >>= 1) {
        if ((int)threadIdx.x < o) red[threadIdx.x] += red[threadIdx.x + o];
        __syncthreads();
    }
    if (threadIdx.x == 0) g_colsum[d] = red[0];
}

// ---------------- main kernel ----------------
#define STG   35840
#define VOFF  17408
enum { SMTOT = 2 * STG + 512 };

__device__ __forceinline__ void issue_tile(uint32_t sb, int stg, int t, int tid) {
    uint32_t kb = sb + stg * STG;
    uint32_t vb = kb + VOFF;
    const __half* ks = g_Kh + (size_t)t * BK * DIM;
    const __half* vs = g_Vt + (size_t)t * BK;
    #pragma unroll
    for (int c = 0; c < 8; ++c) {
        int chunk = c * NTHREADS + tid;
        int r = chunk >> 4, o = chunk & 15;
        cp16(kb + r * SROWK + o * 16, ks + (size_t)r * DIM + o * 8);
    }
    #pragma unroll
    for (int c = 0; c < 8; ++c) {
        int chunk = c * NTHREADS + tid;
        int r = chunk >> 3, o = chunk & 7;
        cp16(vb + r * SROWV + o * 16, vs + (size_t)r * NKEY + o * 8);
    }
}

__global__ __launch_bounds__(NTHREADS, 2)
void mb_main() {
    extern __shared__ char sm[];
    const uint32_t sb = smem_u32(sm);
    const int tid = threadIdx.x, wid = tid >> 5, lane = tid & 31;
    const int qt = blockIdx.x >> 2;        // Q tile
    const int sp = blockIdx.x & 3;         // key split
    const int t0 = sp * TPS;

    // Stage this CTA's 128-row Q tile into stage-0 region.
    {
        const __half* qs = g_Qh + (size_t)qt * BM * DIM;
        #pragma unroll
        for (int c = 0; c < 16; ++c) {
            int chunk = c * NTHREADS + tid;
            int r = chunk >> 4, o = chunk & 15;
            *(uint4*)(sm + r * SROWK + o * 16) =
                *(const uint4*)(qs + (size_t)r * DIM + o * 8);
        }
    }
    __syncthreads();
    uint32_t qa[2][8][4];
    {
        int colh = (lane >> 4) * 8;
        #pragma unroll
        for (int rb = 0; rb < 2; ++rb) {
            int row = wid * 32 + rb * 16 + (lane & 15);
            #pragma unroll
            for (int k = 0; k < 8; ++k)
                ldsm4(qa[rb][k], sb + row * SROWK + (k * 16 + colh) * 2);
        }
    }
    __syncthreads();
    issue_tile(sb, 0, t0, tid); CP_COMMIT();

    float o_acc[2][16][4];
    #pragma unroll
    for (int rb = 0; rb < 2; ++rb)
        #pragma unroll
        for (int j = 0; j < 16; ++j)
            #pragma unroll
            for (int c = 0; c < 4; ++c) o_acc[rb][j][c] = 0.f;
    float zlo[2] = {0.f, 0.f}, zhi[2] = {0.f, 0.f};

    const int bg = (lane >> 3) & 1, bc = (lane >> 4), br = lane & 7;
    const int krow = bg * 8 + br;

    for (int i = 0; i < TPS; ++i) {
        int stg = i & 1;
        CP_WAIT0();
        __syncthreads();
        if (i + 1 < TPS) issue_tile(sb, stg ^ 1, t0 + i + 1, tid);
        CP_COMMIT();

        uint32_t kb = sb + stg * STG;
        uint32_t vb = kb + VOFF;

        #pragma unroll
        for (int s = 0; s < 4; ++s) {
            float c0[2][4] = {{0,0,0,0},{0,0,0,0}};
            float c1[2][4] = {{0,0,0,0},{0,0,0,0}};
            #pragma unroll
            for (int k = 0; k < 8; ++k) {
                uint32_t kf[4];
                ldsm4(kf, kb + (uint32_t)((s * 16 + krow) * SROWK + (k * 16 + bc * 8) * 2));
                mma16816(c0[0], qa[0][k], kf[0], kf[2]);
                mma16816(c1[0], qa[0][k], kf[1], kf[3]);
                mma16816(c0[1], qa[1][k], kf[0], kf[2]);
                mma16816(c1[1], qa[1][k], kf[1], kf[3]);
            }
            uint32_t pa[2][4];
            #pragma unroll
            for (int rb = 0; rb < 2; ++rb) {
                float p00 = ex2(c0[rb][0]) - 1.f, p01 = ex2(c0[rb][1]) - 1.f;
                float p02 = ex2(c0[rb][2]) - 1.f, p03 = ex2(c0[rb][3]) - 1.f;
                float p10 = ex2(c1[rb][0]) - 1.f, p11 = ex2(c1[rb][1]) - 1.f;
                float p12 = ex2(c1[rb][2]) - 1.f, p13 = ex2(c1[rb][3]) - 1.f;
                zlo[rb] += (p00 + p01) + (p10 + p11);
                zhi[rb] += (p02 + p03) + (p12 + p13);
                pa[rb][0] = packh(p01, p00);
                pa[rb][1] = packh(p03, p02);
                pa[rb][2] = packh(p11, p10);
                pa[rb][3] = packh(p13, p12);
            }
            #pragma unroll
            for (int j = 0; j < 8; ++j) {
                uint32_t vf[4];
                ldsm4(vf, vb + (uint32_t)((j * 16 + krow) * SROWV + (s * 16 + bc * 8) * 2));
                mma16816(o_acc[0][2 * j],     pa[0], vf[0], vf[2]);
                mma16816(o_acc[0][2 * j + 1], pa[0], vf[1], vf[3]);
                mma16816(o_acc[1][2 * j],     pa[1], vf[0], vf[2]);
                mma16816(o_acc[1][2 * j + 1], pa[1], vf[1], vf[3]);
            }
        }
    }

    // ---- epilogue: write RAW partials (no colsum, no normalize) ----
    float* op = g_Op[sp];
    int col0 = (lane & 3) * 2;
    #pragma unroll
    for (int rb = 0; rb < 2; ++rb) {
        float zl = zlo[rb], zh = zhi[rb];
        zl += __shfl_xor_sync(0xffffffffu, zl, 1);
        zl += __shfl_xor_sync(0xffffffffu, zl, 2);
        zh += __shfl_xor_sync(0xffffffffu, zh, 1);
        zh += __shfl_xor_sync(0xffffffffu, zh, 2);
        size_t row0 = (size_t)qt * BM + wid * 32 + rb * 16 + (lane >> 2);
        if ((lane & 3) == 0) {
            g_Zp[sp][row0] = zl;
            g_Zp[sp][row0 + 8] = zh;
        }
        #pragma unroll
        for (int j = 0; j < 16; ++j) {
            int c = j * 8 + col0;
            *(float2*)&op[row0 * DIM + c] = make_float2(o_acc[rb][j][0], o_acc[rb][j][1]);
            *(float2*)&op[(row0 + 8) * DIM + c] = make_float2(o_acc[rb][j][2], o_acc[rb][j][3]);
        }
    }
}

// ---------------- combine kernel ----------------
__global__ void mb_combine(float* __restrict__ out) {
    // 8192 blocks x 256 threads; block handles 8 rows, thread does 4 cols.
    int r = blockIdx.x * 8 + (threadIdx.x >> 5);
    int c = (threadIdx.x & 31) * 4;
    float z = (float)NKEY + g_Zp[0][r] + g_Zp[1][r] + g_Zp[2][r] + g_Zp[3][r];
    float inv = 1.0f / z;
    size_t off = (size_t)r * DIM + c;
    float4 a0 = *(const float4*)&g_Op[0][off];
    float4 a1 = *(const float4*)&g_Op[1][off];
    float4 a2 = *(const float4*)&g_Op[2][off];
    float4 a3 = *(const float4*)&g_Op[3][off];
    float4 cs = *(const float4*)&g_colsum[c];
    float4 o;
    o.x = (cs.x + a0.x + a1.x + a2.x + a3.x) * inv;
    o.y = (cs.y + a0.y + a1.y + a2.y + a3.y) * inv;
    o.z = (cs.z + a0.z + a1.z + a2.z + a3.z) * inv;
    o.w = (cs.w + a0.w + a1.w + a2.w + a3.w) * inv;
    *(float4*)&out[off] = o;
}

// ---------------- launch ----------------
extern "C" void kernel_launch(void* const* d_in, const int* in_sizes, int n_in,
                              void* d_out, int out_size) {
    const float* queries = (const float*)d_in[0];
    const float* keys    = (const float*)d_in[1];
    float* out = (float*)d_out;
    int N = in_sizes[0] / DIM;

    prep_q<<<N / 8, 256>>>(queries);
    prep_k<<<NKEY / 8, 256>>>(keys);
    prep_colsum<<<DIM, 256>>>(keys);

    cudaFuncSetAttribute(mb_main, cudaFuncAttributeMaxDynamicSharedMemorySize, SMTOT);
    mb_main<<<(N / BM) * NSPLIT, NTHREADS, SMTOT>>>();
    mb_combine<<<N / 8, 256>>>(out);
}

// round 15
// speedup vs baseline: 1.1207x; 1.0217x over previous
#include <cuda_runtime.h>
#include <cuda_fp16.h>
#include <cstdint>

// out = softmax(normalize(Q)@normalize(K)^T) @ K,  N=65536, K=4096, D=128, fp32
// fp16 mma.sync dataflow, R13 split-K x4 (proven, rel_err 9.5e-5).
// R14: (A) S-GEMM with fp16 accumulators (probe: is fp32-accum half-rate?)
//      (B) split-K partials stored fp16 (halves combine traffic).

#define NQ 65536
#define NKEY 4096
#define DIM 128
#define BM 128            // 4 warps x 32 rows
#define BK 64
#define NSPLIT 4
#define TPS (NKEY / BK / NSPLIT)   // 16 tiles per split
#define NTHREADS 128
#define SROWK 272
#define SROWV 144

__device__ __align__(16) __half g_Qh[(size_t)NQ * DIM];    // normalized Q * log2e
__device__ __align__(16) __half g_Kh[(size_t)NKEY * DIM];  // NORMALIZED keys
__device__ __align__(16) __half g_Vt[(size_t)DIM * NKEY];  // raw keys^T [d][key]
__device__ __align__(16) float  g_colsum[DIM];
__device__ __align__(16) __half g_OpH[NSPLIT][(size_t)NQ * DIM];  // fp16 partials
__device__ __align__(16) float  g_Zp[NSPLIT][NQ];                 // partial Z

// ---------------- helpers ----------------
__device__ __forceinline__ uint32_t smem_u32(const void* p) {
    uint32_t a;
    asm("{ .reg .u64 t; cvta.to.shared.u64 t, %1; cvt.u32.u64 %0, t; }" : "=r"(a) : "l"(p));
    return a;
}
__device__ __forceinline__ float ex2(float x) {
    float y; asm("ex2.approx.f32 %0, %1;" : "=f"(y) : "f"(x)); return y;
}
__device__ __forceinline__ void ldsm4(uint32_t* r, uint32_t addr) {
    asm volatile("ldmatrix.sync.aligned.m8n8.x4.shared.b16 {%0,%1,%2,%3}, [%4];"
                 : "=r"(r[0]), "=r"(r[1]), "=r"(r[2]), "=r"(r[3]) : "r"(addr));
}
// fp32-accum MMA (PV)
__device__ __forceinline__ void mma16816(float* d, const uint32_t* a, uint32_t b0, uint32_t b1) {
    asm volatile("mma.sync.aligned.m16n8k16.row.col.f32.f16.f16.f32 "
                 "{%0,%1,%2,%3}, {%4,%5,%6,%7}, {%8,%9}, {%0,%1,%2,%3};"
                 : "+f"(d[0]), "+f"(d[1]), "+f"(d[2]), "+f"(d[3])
                 : "r"(a[0]), "r"(a[1]), "r"(a[2]), "r"(a[3]), "r"(b0), "r"(b1));
}
// fp16-accum MMA (S probe): D/C = 2 regs of f16x2 ({c0,c1},{c2,c3})
__device__ __forceinline__ void mma16816h(uint32_t* d, const uint32_t* a, uint32_t b0, uint32_t b1) {
    asm volatile("mma.sync.aligned.m16n8k16.row.col.f16.f16.f16.f16 "
                 "{%0,%1}, {%2,%3,%4,%5}, {%6,%7}, {%0,%1};"
                 : "+r"(d[0]), "+r"(d[1])
                 : "r"(a[0]), "r"(a[1]), "r"(a[2]), "r"(a[3]), "r"(b0), "r"(b1));
}
__device__ __forceinline__ uint32_t packh(float hi, float lo) {
    uint32_t r; asm("cvt.rn.f16x2.f32 %0, %1, %2;" : "=r"(r) : "f"(hi), "f"(lo)); return r;
}
__device__ __forceinline__ void cp16(uint32_t saddr, const void* g) {
    asm volatile("cp.async.cg.shared.global [%0], [%1], 16;" :: "r"(saddr), "l"(g));
}
#define CP_COMMIT() asm volatile("cp.async.commit_group;" ::: "memory")
#define CP_WAIT0()  asm volatile("cp.async.wait_group 0;" ::: "memory")

// ---------------- prep kernels ----------------
__global__ void prep_q(const float* __restrict__ q) {
    int row = blockIdx.x * 8 + (threadIdx.x >> 5);
    int lane = threadIdx.x & 31;
    float4 v = ((const float4*)q)[(size_t)row * 32 + lane];
    float ss = v.x * v.x + v.y * v.y + v.z * v.z + v.w * v.w;
    #pragma unroll
    for (int o = 16; o > 0; o >>= 1) ss += __shfl_xor_sync(0xffffffffu, ss, o);
    float sc = 1.44269504f / fmaxf(sqrtf(ss), 1e-12f);   // fold log2(e)
    __half2* dst = (__half2*)(g_Qh + (size_t)row * DIM + lane * 4);
    dst[0] = __float22half2_rn(make_float2(v.x * sc, v.y * sc));
    dst[1] = __float22half2_rn(make_float2(v.z * sc, v.w * sc));
}

__global__ void prep_k(const float* __restrict__ keys) {
    int row = blockIdx.x * 8 + (threadIdx.x >> 5);
    int lane = threadIdx.x & 31;
    float4 v = ((const float4*)keys)[(size_t)row * 32 + lane];
    float ss = v.x * v.x + v.y * v.y + v.z * v.z + v.w * v.w;
    #pragma unroll
    for (int o = 16; o > 0; o >>= 1) ss += __shfl_xor_sync(0xffffffffu, ss, o);
    float sc = 1.0f / fmaxf(sqrtf(ss), 1e-12f);
    __half2* dst = (__half2*)(g_Kh + (size_t)row * DIM + lane * 4);
    dst[0] = __float22half2_rn(make_float2(v.x * sc, v.y * sc));
    dst[1] = __float22half2_rn(make_float2(v.z * sc, v.w * sc));
    float xs[4] = {v.x, v.y, v.z, v.w};
    #pragma unroll
    for (int j = 0; j < 4; ++j)
        g_Vt[(size_t)(lane * 4 + j) * NKEY + row] = __float2half(xs[j]);
}

__global__ void prep_colsum(const float* __restrict__ keys) {
    __shared__ float red[256];
    int d = blockIdx.x;
    float s = 0.f;
    for (int k = threadIdx.x; k < NKEY; k += 256) s += keys[(size_t)k * DIM + d];
    red[threadIdx.x] = s;
    __syncthreads();
    for (int o = 128; o > 0; o >>= 1) {
        if ((int)threadIdx.x < o) red[threadIdx.x] += red[threadIdx.x + o];
        __syncthreads();
    }
    if (threadIdx.x == 0) g_colsum[d] = red[0];
}

// ---------------- main kernel ----------------
#define STG   35840
#define VOFF  17408
enum { SMTOT = 2 * STG + 512 };

__device__ __forceinline__ void issue_tile(uint32_t sb, int stg, int t, int tid) {
    uint32_t kb = sb + stg * STG;
    uint32_t vb = kb + VOFF;
    const __half* ks = g_Kh + (size_t)t * BK * DIM;
    const __half* vs = g_Vt + (size_t)t * BK;
    #pragma unroll
    for (int c = 0; c < 8; ++c) {
        int chunk = c * NTHREADS + tid;
        int r = chunk >> 4, o = chunk & 15;
        cp16(kb + r * SROWK + o * 16, ks + (size_t)r * DIM + o * 8);
    }
    #pragma unroll
    for (int c = 0; c < 8; ++c) {
        int chunk = c * NTHREADS + tid;
        int r = chunk >> 3, o = chunk & 7;
        cp16(vb + r * SROWV + o * 16, vs + (size_t)r * NKEY + o * 8);
    }
}

__global__ __launch_bounds__(NTHREADS, 2)
void mb_main() {
    extern __shared__ char sm[];
    const uint32_t sb = smem_u32(sm);
    const int tid = threadIdx.x, wid = tid >> 5, lane = tid & 31;
    const int qt = blockIdx.x >> 2;        // Q tile
    const int sp = blockIdx.x & 3;         // key split
    const int t0 = sp * TPS;

    // Stage this CTA's 128-row Q tile into stage-0 region.
    {
        const __half* qs = g_Qh + (size_t)qt * BM * DIM;
        #pragma unroll
        for (int c = 0; c < 16; ++c) {
            int chunk = c * NTHREADS + tid;
            int r = chunk >> 4, o = chunk & 15;
            *(uint4*)(sm + r * SROWK + o * 16) =
                *(const uint4*)(qs + (size_t)r * DIM + o * 8);
        }
    }
    __syncthreads();
    uint32_t qa[2][8][4];
    {
        int colh = (lane >> 4) * 8;
        #pragma unroll
        for (int rb = 0; rb < 2; ++rb) {
            int row = wid * 32 + rb * 16 + (lane & 15);
            #pragma unroll
            for (int k = 0; k < 8; ++k)
                ldsm4(qa[rb][k], sb + row * SROWK + (k * 16 + colh) * 2);
        }
    }
    __syncthreads();
    issue_tile(sb, 0, t0, tid); CP_COMMIT();

    float o_acc[2][16][4];
    #pragma unroll
    for (int rb = 0; rb < 2; ++rb)
        #pragma unroll
        for (int j = 0; j < 16; ++j)
            #pragma unroll
            for (int c = 0; c < 4; ++c) o_acc[rb][j][c] = 0.f;
    float zlo[2] = {0.f, 0.f}, zhi[2] = {0.f, 0.f};

    const int bg = (lane >> 3) & 1, bc = (lane >> 4), br = lane & 7;
    const int krow = bg * 8 + br;

    for (int i = 0; i < TPS; ++i) {
        int stg = i & 1;
        CP_WAIT0();
        __syncthreads();
        if (i + 1 < TPS) issue_tile(sb, stg ^ 1, t0 + i + 1, tid);
        CP_COMMIT();

        uint32_t kb = sb + stg * STG;
        uint32_t vb = kb + VOFF;

        #pragma unroll
        for (int s = 0; s < 4; ++s) {
            // ---- S: fp16-accum MMAs (probe) ----
            uint32_t d0[2][2] = {{0u,0u},{0u,0u}};   // [rb][reg]: n8-tile A
            uint32_t d1[2][2] = {{0u,0u},{0u,0u}};   // [rb][reg]: n8-tile B
            #pragma unroll
            for (int k = 0; k < 8; ++k) {
                uint32_t kf[4];
                ldsm4(kf, kb + (uint32_t)((s * 16 + krow) * SROWK + (k * 16 + bc * 8) * 2));
                mma16816h(d0[0], qa[0][k], kf[0], kf[2]);
                mma16816h(d1[0], qa[0][k], kf[1], kf[3]);
                mma16816h(d0[1], qa[1][k], kf[0], kf[2]);
                mma16816h(d1[1], qa[1][k], kf[1], kf[3]);
            }
            // ---- ex2(s)-1, Z partials, pack PV A-fragments ----
            uint32_t pa[2][4];
            #pragma unroll
            for (int rb = 0; rb < 2; ++rb) {
                float2 s01 = __half22float2(*(__half2*)&d0[rb][0]);
                float2 s23 = __half22float2(*(__half2*)&d0[rb][1]);
                float2 t01 = __half22float2(*(__half2*)&d1[rb][0]);
                float2 t23 = __half22float2(*(__half2*)&d1[rb][1]);
                float p00 = ex2(s01.x) - 1.f, p01 = ex2(s01.y) - 1.f;
                float p02 = ex2(s23.x) - 1.f, p03 = ex2(s23.y) - 1.f;
                float p10 = ex2(t01.x) - 1.f, p11 = ex2(t01.y) - 1.f;
                float p12 = ex2(t23.x) - 1.f, p13 = ex2(t23.y) - 1.f;
                zlo[rb] += (p00 + p01) + (p10 + p11);
                zhi[rb] += (p02 + p03) + (p12 + p13);
                pa[rb][0] = packh(p01, p00);
                pa[rb][1] = packh(p03, p02);
                pa[rb][2] = packh(p11, p10);
                pa[rb][3] = packh(p13, p12);
            }
            // ---- O += P @ V (fp32 accum) ----
            #pragma unroll
            for (int j = 0; j < 8; ++j) {
                uint32_t vf[4];
                ldsm4(vf, vb + (uint32_t)((j * 16 + krow) * SROWV + (s * 16 + bc * 8) * 2));
                mma16816(o_acc[0][2 * j],     pa[0], vf[0], vf[2]);
                mma16816(o_acc[0][2 * j + 1], pa[0], vf[1], vf[3]);
                mma16816(o_acc[1][2 * j],     pa[1], vf[0], vf[2]);
                mma16816(o_acc[1][2 * j + 1], pa[1], vf[1], vf[3]);
            }
        }
    }

    // ---- epilogue: write fp16 partials ----
    __half* op = g_OpH[sp];
    int col0 = (lane & 3) * 2;
    #pragma unroll
    for (int rb = 0; rb < 2; ++rb) {
        float zl = zlo[rb], zh = zhi[rb];
        zl += __shfl_xor_sync(0xffffffffu, zl, 1);
        zl += __shfl_xor_sync(0xffffffffu, zl, 2);
        zh += __shfl_xor_sync(0xffffffffu, zh, 1);
        zh += __shfl_xor_sync(0xffffffffu, zh, 2);
        size_t row0 = (size_t)qt * BM + wid * 32 + rb * 16 + (lane >> 2);
        if ((lane & 3) == 0) {
            g_Zp[sp][row0] = zl;
            g_Zp[sp][row0 + 8] = zh;
        }
        #pragma unroll
        for (int j = 0; j < 16; ++j) {
            int c = j * 8 + col0;
            *(__half2*)&op[row0 * DIM + c] =
                __floats2half2_rn(o_acc[rb][j][0], o_acc[rb][j][1]);
            *(__half2*)&op[(row0 + 8) * DIM + c] =
                __floats2half2_rn(o_acc[rb][j][2], o_acc[rb][j][3]);
        }
    }
}

// ---------------- combine kernel ----------------
__global__ void mb_combine(float* __restrict__ out) {
    int r = blockIdx.x * 8 + (threadIdx.x >> 5);
    int c = (threadIdx.x & 31) * 4;
    float z = (float)NKEY + g_Zp[0][r] + g_Zp[1][r] + g_Zp[2][r] + g_Zp[3][r];
    float inv = 1.0f / z;
    size_t off = (size_t)r * DIM + c;
    float acc[4] = {g_colsum[c], g_colsum[c + 1], g_colsum[c + 2], g_colsum[c + 3]};
    #pragma unroll
    for (int sp = 0; sp < NSPLIT; ++sp) {
        uint2 raw = *(const uint2*)&g_OpH[sp][off];
        float2 a = __half22float2(*(__half2*)&raw.x);
        float2 b = __half22float2(*(__half2*)&raw.y);
        acc[0] += a.x; acc[1] += a.y; acc[2] += b.x; acc[3] += b.y;
    }
    *(float4*)&out[off] = make_float4(acc[0] * inv, acc[1] * inv, acc[2] * inv, acc[3] * inv);
}

// ---------------- launch ----------------
extern "C" void kernel_launch(void* const* d_in, const int* in_sizes, int n_in,
                              void* d_out, int out_size) {
    const float* queries = (const float*)d_in[0];
    const float* keys    = (const float*)d_in[1];
    float* out = (float*)d_out;
    int N = in_sizes[0] / DIM;

    prep_q<<<N / 8, 256>>>(queries);
    prep_k<<<NKEY / 8, 256>>>(keys);
    prep_colsum<<<DIM, 256>>>(keys);

    cudaFuncSetAttribute(mb_main, cudaFuncAttributeMaxDynamicSharedMemorySize, SMTOT);
    mb_main<<<(N / BM) * NSPLIT, NTHREADS, SMTOT>>>();
    mb_combine<<<N / 8, 256>>>(out);
}